// round 3
// baseline (speedup 1.0000x reference)
#include <cuda_runtime.h>

#define IN_SZ  448
#define OUT_SZ 224
#define BATCH  64
#define ROWS_PER_BLK 8

// Per-(image, output index) coefficients (mask folded in):
//  col: a=(a0,a1) with a0=(1-wc)*mcol[c0], a1=wc*mcol[c1]; c=(c0,c1)
//  row: b=(b0,b1) with b0=(1-wr)*mrow[r0], b1=wr*mrow[r1]; r=(r0,r1)
__device__ float2 g_a[BATCH * OUT_SZ];
__device__ int2   g_c[BATCH * OUT_SZ];
__device__ float2 g_b[BATCH * OUT_SZ];
__device__ int2   g_r[BATCH * OUT_SZ];
__device__ int    g_cbase[BATCH];   // window col start, 128B-aligned
__device__ int    g_chi[BATCH];     // window col end (inclusive)

__device__ __forceinline__ float sig10(float z) {
    return 1.0f / (1.0f + __expf(-10.0f * z));
}

// ---------------------------------------------------------------------------
// Prologue: coefficients. grid=64, block=224. Tiny.
// ---------------------------------------------------------------------------
__global__ void racnn_coef_kernel(const float* __restrict__ locs) {
    const int b = blockIdx.x;
    const int j = threadIdx.x;            // 0..223

    float tx = locs[b * 3 + 0];
    float ty = locs[b * 3 + 1];
    float tl = locs[b * 3 + 2];

    tl = fmaxf(tl, 448.0f / 3.0f);
    tx = fminf(fmaxf(tx, tl), 448.0f - tl);
    ty = fminf(fmaxf(ty, tl), 448.0f - tl);

    const float w_off = fmaxf(floorf(tx - tl), 0.0f);
    const float h_off = fmaxf(floorf(ty - tl), 0.0f);
    const float w_end = fminf(floorf(tx + tl), 448.0f);
    const float h_end = fminf(floorf(ty + tl), 448.0f);

    const float fj = (float)j;

    // row side (uses w_off/w_end per reference)
    {
        const float step = (w_end - w_off - 1.0f) * (1.0f / 223.0f);
        const float src  = w_off + fj * step;
        const float r0f  = fminf(fmaxf(floorf(src), 0.0f), 447.0f);
        const float wr   = src - r0f;
        const int   r0   = (int)r0f;
        const int   r1   = min(r0 + 1, IN_SZ - 1);
        const float mr0  = sig10(r0f - w_off) - sig10(r0f - w_end);
        const float mr1  = sig10((float)r1 - w_off) - sig10((float)r1 - w_end);
        g_b[b * OUT_SZ + j] = make_float2((1.0f - wr) * mr0, wr * mr1);
        g_r[b * OUT_SZ + j] = make_int2(r0, r1);
    }

    // column side (uses h_off/h_end)
    {
        const float step = (h_end - h_off - 1.0f) * (1.0f / 223.0f);
        const float src  = h_off + fj * step;
        const float c0f  = fminf(fmaxf(floorf(src), 0.0f), 447.0f);
        const float wc   = src - c0f;
        const int   c0   = (int)c0f;
        const int   c1   = min(c0 + 1, IN_SZ - 1);
        const float mc0  = sig10(c0f - h_off) - sig10(c0f - h_end);
        const float mc1  = sig10((float)c1 - h_off) - sig10((float)c1 - h_end);
        g_a[b * OUT_SZ + j] = make_float2((1.0f - wc) * mc0, wc * mc1);
        g_c[b * OUT_SZ + j] = make_int2(c0, c1);

        // src_c is monotone increasing in j -> j=0 gives min c0, j=223 max c1
        if (j == 0)   g_cbase[b] = c0 & ~31;   // 128B aligned
        if (j == 223) g_chi[b]   = c1;
    }
}

// ---------------------------------------------------------------------------
// Main: phase 1 vertical combine (coalesced) -> smem; phase 2 horizontal
// gather (2 LDS + 2 FMA per pixel). One block = (b, ch, 8 output rows).
// ---------------------------------------------------------------------------
__global__ __launch_bounds__(448) void racnn_resize_kernel(
    const float* __restrict__ img, float* __restrict__ out)
{
    __shared__ float T[ROWS_PER_BLK * IN_SZ];   // 14336 B

    const int b  = blockIdx.z;
    const int ch = blockIdx.y;
    const int jr_base = blockIdx.x * ROWS_PER_BLK;
    const int tid = threadIdx.y * OUT_SZ + threadIdx.x;   // 0..447

    const int c_base = g_cbase[b];
    const int count  = g_chi[b] - c_base + 1;             // <= 448

    const float* base = img + (size_t)(b * 3 + ch) * (IN_SZ * IN_SZ) + c_base;

    // ---- Phase 1: T[k][c] = b0*img[r0][c] + b1*img[r1][c], coalesced ----
    if (tid < count) {
        #pragma unroll
        for (int k = 0; k < ROWS_PER_BLK; k++) {
            const int2   r  = __ldg(&g_r[b * OUT_SZ + jr_base + k]);  // uniform
            const float2 bb = __ldg(&g_b[b * OUT_SZ + jr_base + k]);  // uniform
            const float v0 = __ldg(base + r.x * IN_SZ + tid);
            const float v1 = __ldg(base + r.y * IN_SZ + tid);
            T[k * IN_SZ + tid] = fmaf(bb.y, v1, bb.x * v0);
        }
    }
    __syncthreads();

    // ---- Phase 2: res = a0*T[c0] + a1*T[c1] ----
    const int jc = threadIdx.x;
    const float2 a = __ldg(&g_a[b * OUT_SZ + jc]);
    const int2   c = __ldg(&g_c[b * OUT_SZ + jc]);
    const int c0r = c.x - c_base;
    const int c1r = c.y - c_base;

    float* orow = out + ((size_t)(b * 3 + ch) * OUT_SZ + jr_base + threadIdx.y * 4) * OUT_SZ + jc;
    const int koff = threadIdx.y * 4;

    #pragma unroll
    for (int k4 = 0; k4 < 4; k4++) {
        const float t0 = T[(koff + k4) * IN_SZ + c0r];
        const float t1 = T[(koff + k4) * IN_SZ + c1r];
        orow[k4 * OUT_SZ] = fmaf(a.y, t1, a.x * t0);
    }
}

// ---------------------------------------------------------------------------
extern "C" void kernel_launch(void* const* d_in, const int* in_sizes, int n_in,
                              void* d_out, int out_size)
{
    const float* images = (const float*)d_in[0];
    const float* locs   = (const float*)d_in[1];
    if (n_in >= 2 && in_sizes[0] == BATCH * 3) {
        locs   = (const float*)d_in[0];
        images = (const float*)d_in[1];
    }
    float* out = (float*)d_out;

    racnn_coef_kernel<<<BATCH, OUT_SZ>>>(locs);

    dim3 block(OUT_SZ, 2, 1);                        // 448 threads
    dim3 grid(OUT_SZ / ROWS_PER_BLK, 3, BATCH);      // (28, 3, 64)
    racnn_resize_kernel<<<grid, block>>>(images, out);
}

// round 4
// speedup vs baseline: 1.2221x; 1.2221x over previous
#include <cuda_runtime.h>

#define IN_SZ   448
#define OUT_SZ  224
#define BATCH   64
#define RPB     8           // output rows per block
#define PLANE   (IN_SZ * IN_SZ)

__device__ __forceinline__ float sig10(float z) {
    return 1.0f / (1.0f + __expf(-10.0f * z));
}

// One block = (image b, 8 output rows, ALL 3 channels). 448 threads.
// Phase 0: coefficients in smem. Phase 1: vertical combine (coalesced LDG).
// Phase 2: horizontal combine (2 LDS + 2 FMA per pixel).
__global__ __launch_bounds__(448) void racnn_fused_kernel(
    const float* __restrict__ img, const float* __restrict__ locs,
    float* __restrict__ out)
{
    __shared__ float  T[3 * RPB * IN_SZ];   // 43008 B
    __shared__ float2 sA[OUT_SZ];
    __shared__ int2   sC[OUT_SZ];
    __shared__ float2 sB[RPB];
    __shared__ int    sR0[RPB], sR1[RPB];
    __shared__ int    sCbase, sChi;

    const int b       = blockIdx.y;
    const int jr_base = blockIdx.x * RPB;
    const int tid     = threadIdx.x;        // 0..447

    // ---------------- Phase 0: coefficients ----------------
    float tx = __ldg(&locs[b * 3 + 0]);
    float ty = __ldg(&locs[b * 3 + 1]);
    float tl = __ldg(&locs[b * 3 + 2]);

    tl = fmaxf(tl, 448.0f / 3.0f);
    tx = fminf(fmaxf(tx, tl), 448.0f - tl);
    ty = fminf(fmaxf(ty, tl), 448.0f - tl);

    const float w_off = fmaxf(floorf(tx - tl), 0.0f);
    const float h_off = fmaxf(floorf(ty - tl), 0.0f);
    const float w_end = fminf(floorf(tx + tl), 448.0f);
    const float h_end = fminf(floorf(ty + tl), 448.0f);

    if (tid < OUT_SZ) {
        // column side (h axis)
        const float fj   = (float)tid;
        const float step = (h_end - h_off - 1.0f) * (1.0f / 223.0f);
        const float src  = h_off + fj * step;
        const float c0f  = fminf(fmaxf(floorf(src), 0.0f), 447.0f);
        const float wc   = src - c0f;
        const int   c0   = (int)c0f;
        const int   c1   = min(c0 + 1, IN_SZ - 1);
        const float mc0  = sig10(c0f - h_off) - sig10(c0f - h_end);
        const float mc1  = sig10((float)c1 - h_off) - sig10((float)c1 - h_end);
        sA[tid] = make_float2((1.0f - wc) * mc0, wc * mc1);
        sC[tid] = make_int2(c0, c1);
        if (tid == 0)   sCbase = c0 & ~31;   // min over j (src monotone inc.)
        if (tid == 223) sChi   = c1;         // max over j
    } else if (tid < OUT_SZ + RPB) {
        // row side (w axis) for this block's 8 output rows
        const int   k    = tid - OUT_SZ;
        const float fj   = (float)(jr_base + k);
        const float step = (w_end - w_off - 1.0f) * (1.0f / 223.0f);
        const float src  = w_off + fj * step;
        const float r0f  = fminf(fmaxf(floorf(src), 0.0f), 447.0f);
        const float wr   = src - r0f;
        const int   r0   = (int)r0f;
        const int   r1   = min(r0 + 1, IN_SZ - 1);
        const float mr0  = sig10(r0f - w_off) - sig10(r0f - w_end);
        const float mr1  = sig10((float)r1 - w_off) - sig10((float)r1 - w_end);
        sB[k]  = make_float2((1.0f - wr) * mr0, wr * mr1);
        sR0[k] = r0;
        sR1[k] = r1;
    }
    __syncthreads();

    // ---------------- Phase 1: vertical combine, coalesced ----------------
    const int c_base = sCbase;
    const int count  = sChi - c_base + 1;    // <= 448

    if (tid < count) {
        const float* base_t = img + (size_t)b * 3 * PLANE + c_base + tid;
        #pragma unroll
        for (int k = 0; k < RPB; k++) {
            const int    r0 = sR0[k];
            const int    r1 = sR1[k];
            const float2 bb = sB[k];
            const float* p0 = base_t + r0 * IN_SZ;
            const float* p1 = base_t + r1 * IN_SZ;
            // 3 channels: independent loads, big MLP
            const float a0 = __ldg(p0);
            const float a1 = __ldg(p1);
            const float b0 = __ldg(p0 + PLANE);
            const float b1 = __ldg(p1 + PLANE);
            const float c0v = __ldg(p0 + 2 * PLANE);
            const float c1v = __ldg(p1 + 2 * PLANE);
            T[(0 * RPB + k) * IN_SZ + tid] = fmaf(bb.y, a1, bb.x * a0);
            T[(1 * RPB + k) * IN_SZ + tid] = fmaf(bb.y, b1, bb.x * b0);
            T[(2 * RPB + k) * IN_SZ + tid] = fmaf(bb.y, c1v, bb.x * c0v);
        }
    }
    __syncthreads();

    // ---------------- Phase 2: horizontal combine ----------------
    const int half = (tid >= OUT_SZ) ? 1 : 0;
    const int jc   = tid - half * OUT_SZ;
    const int koff = half * 4;

    const float2 a = sA[jc];
    const int2   c = sC[jc];
    const int c0r  = c.x - c_base;
    const int c1r  = c.y - c_base;

    float* obase = out + (size_t)b * 3 * OUT_SZ * OUT_SZ
                       + (size_t)(jr_base + koff) * OUT_SZ + jc;

    #pragma unroll
    for (int ch = 0; ch < 3; ch++) {
        #pragma unroll
        for (int k4 = 0; k4 < 4; k4++) {
            const float t0 = T[(ch * RPB + koff + k4) * IN_SZ + c0r];
            const float t1 = T[(ch * RPB + koff + k4) * IN_SZ + c1r];
            obase[(size_t)ch * OUT_SZ * OUT_SZ + k4 * OUT_SZ] =
                fmaf(a.y, t1, a.x * t0);
        }
    }
}

// ---------------------------------------------------------------------------
extern "C" void kernel_launch(void* const* d_in, const int* in_sizes, int n_in,
                              void* d_out, int out_size)
{
    const float* images = (const float*)d_in[0];
    const float* locs   = (const float*)d_in[1];
    if (n_in >= 2 && in_sizes[0] == BATCH * 3) {
        locs   = (const float*)d_in[0];
        images = (const float*)d_in[1];
    }
    float* out = (float*)d_out;

    dim3 block(448, 1, 1);
    dim3 grid(OUT_SZ / RPB, BATCH, 1);   // (28, 64)
    racnn_fused_kernel<<<grid, block>>>(images, locs, out);
}

// round 5
// speedup vs baseline: 1.2310x; 1.0072x over previous
#include <cuda_runtime.h>

#define IN_SZ   448
#define OUT_SZ  224
#define BATCH   64
#define RPB     8           // output rows per block
#define PLANE   (IN_SZ * IN_SZ)

__device__ __forceinline__ float sig10(float z) {
    return 1.0f / (1.0f + __expf(-10.0f * z));
}

// Single fused kernel. One block = (image b, channel ch, 8 output rows).
// Phase 0: 232 of 448 threads compute separable coefficients into smem (tiny).
// Phase 1: direct bilinear gather, 16 independent LDGs per thread (4 rows).
__global__ __launch_bounds__(448, 3) void racnn_fused_kernel(
    const float* __restrict__ img, const float* __restrict__ locs,
    float* __restrict__ out)
{
    __shared__ float2 sA[OUT_SZ];     // col: (a0, a1) mask-folded
    __shared__ int2   sC[OUT_SZ];     // col: (c0, c1)
    __shared__ float2 sB[RPB];        // row: (b0, b1) mask-folded
    __shared__ int2   sR[RPB];        // row: (r0, r1)

    const int b       = blockIdx.z;
    const int ch      = blockIdx.y;
    const int jr_base = blockIdx.x * RPB;
    const int tid     = threadIdx.x;          // 0..447

    // ---------------- Phase 0: coefficients ----------------
    if (tid < OUT_SZ + RPB) {
        float tx = __ldg(&locs[b * 3 + 0]);
        float ty = __ldg(&locs[b * 3 + 1]);
        float tl = __ldg(&locs[b * 3 + 2]);

        tl = fmaxf(tl, 448.0f / 3.0f);
        tx = fminf(fmaxf(tx, tl), 448.0f - tl);
        ty = fminf(fmaxf(ty, tl), 448.0f - tl);

        const float w_off = fmaxf(floorf(tx - tl), 0.0f);
        const float h_off = fmaxf(floorf(ty - tl), 0.0f);
        const float w_end = fminf(floorf(tx + tl), 448.0f);
        const float h_end = fminf(floorf(ty + tl), 448.0f);

        if (tid < OUT_SZ) {
            // column side (h axis)
            const float fj   = (float)tid;
            const float step = (h_end - h_off - 1.0f) * (1.0f / 223.0f);
            const float src  = h_off + fj * step;
            const float c0f  = fminf(fmaxf(floorf(src), 0.0f), 447.0f);
            const float wc   = src - c0f;
            const int   c0   = (int)c0f;
            const int   c1   = min(c0 + 1, IN_SZ - 1);
            const float mc0  = sig10(c0f - h_off) - sig10(c0f - h_end);
            const float mc1  = sig10((float)c1 - h_off) - sig10((float)c1 - h_end);
            sA[tid] = make_float2((1.0f - wc) * mc0, wc * mc1);
            sC[tid] = make_int2(c0, c1);
        } else {
            // row side (w axis) for this block's 8 output rows
            const int   k    = tid - OUT_SZ;
            const float fj   = (float)(jr_base + k);
            const float step = (w_end - w_off - 1.0f) * (1.0f / 223.0f);
            const float src  = w_off + fj * step;
            const float r0f  = fminf(fmaxf(floorf(src), 0.0f), 447.0f);
            const float wr   = src - r0f;
            const int   r0   = (int)r0f;
            const int   r1   = min(r0 + 1, IN_SZ - 1);
            const float mr0  = sig10(r0f - w_off) - sig10(r0f - w_end);
            const float mr1  = sig10((float)r1 - w_off) - sig10((float)r1 - w_end);
            sB[k] = make_float2((1.0f - wr) * mr0, wr * mr1);
            sR[k] = make_int2(r0, r1);
        }
    }
    __syncthreads();

    // ---------------- Phase 1: direct gather, 4 rows per thread ----------------
    const int half = (tid >= OUT_SZ) ? 1 : 0;
    const int jc   = tid - half * OUT_SZ;     // 0..223
    const int koff = half * 4;                // rows koff..koff+3

    const float2 a = sA[jc];
    const int2   c = sC[jc];

    const float* base = img + (size_t)(b * 3 + ch) * PLANE;

    // Read row coefs first, then batch all 16 image loads.
    float2 bb[4];
    int2   rr[4];
    #pragma unroll
    for (int k = 0; k < 4; k++) {
        rr[k] = sR[koff + k];
        bb[k] = sB[koff + k];
    }

    float v00[4], v01[4], v10[4], v11[4];
    #pragma unroll
    for (int k = 0; k < 4; k++) {
        const float* row0 = base + rr[k].x * IN_SZ;
        const float* row1 = base + rr[k].y * IN_SZ;
        v00[k] = __ldg(row0 + c.x);
        v01[k] = __ldg(row0 + c.y);
        v10[k] = __ldg(row1 + c.x);
        v11[k] = __ldg(row1 + c.y);
    }

    float* orow = out + ((size_t)(b * 3 + ch) * OUT_SZ + jr_base + koff) * OUT_SZ + jc;

    #pragma unroll
    for (int k = 0; k < 4; k++) {
        const float top = fmaf(a.y, v01[k], a.x * v00[k]);
        const float bot = fmaf(a.y, v11[k], a.x * v10[k]);
        orow[k * OUT_SZ] = fmaf(bb[k].y, bot, bb[k].x * top);
    }
}

// ---------------------------------------------------------------------------
extern "C" void kernel_launch(void* const* d_in, const int* in_sizes, int n_in,
                              void* d_out, int out_size)
{
    const float* images = (const float*)d_in[0];
    const float* locs   = (const float*)d_in[1];
    if (n_in >= 2 && in_sizes[0] == BATCH * 3) {
        locs   = (const float*)d_in[0];
        images = (const float*)d_in[1];
    }
    float* out = (float*)d_out;

    dim3 block(448, 1, 1);
    dim3 grid(OUT_SZ / RPB, 3, BATCH);   // (28, 3, 64)
    racnn_fused_kernel<<<grid, block>>>(images, locs, out);
}

// round 6
// speedup vs baseline: 1.4901x; 1.2105x over previous
#include <cuda_runtime.h>

#define IN_SZ   448
#define OUT_SZ  224
#define BATCH   64
#define PLANE   (IN_SZ * IN_SZ)

// Per-(image, output index) coefficients (mask folded in)
__device__ float2 g_a[BATCH * OUT_SZ];   // col (a0, a1)
__device__ int2   g_c[BATCH * OUT_SZ];   // col (c0, c1)
__device__ float2 g_b[BATCH * OUT_SZ];   // row (b0, b1)
__device__ int2   g_r[BATCH * OUT_SZ];   // row (r0, r1)

__device__ __forceinline__ float sig10(float z) {
    return 1.0f / (1.0f + __expf(-10.0f * z));
}

// ---------------------------------------------------------------------------
// Prologue: coefficients. grid=64, block=224. ~1-2us.
// ---------------------------------------------------------------------------
__global__ void racnn_coef_kernel(const float* __restrict__ locs) {
    const int b = blockIdx.x;
    const int j = threadIdx.x;            // 0..223

    float tx = locs[b * 3 + 0];
    float ty = locs[b * 3 + 1];
    float tl = locs[b * 3 + 2];

    tl = fmaxf(tl, 448.0f / 3.0f);
    tx = fminf(fmaxf(tx, tl), 448.0f - tl);
    ty = fminf(fmaxf(ty, tl), 448.0f - tl);

    const float w_off = fmaxf(floorf(tx - tl), 0.0f);
    const float h_off = fmaxf(floorf(ty - tl), 0.0f);
    const float w_end = fminf(floorf(tx + tl), 448.0f);
    const float h_end = fminf(floorf(ty + tl), 448.0f);

    const float fj = (float)j;

    // row side (w axis)
    {
        const float step = (w_end - w_off - 1.0f) * (1.0f / 223.0f);
        const float src  = w_off + fj * step;
        const float r0f  = fminf(fmaxf(floorf(src), 0.0f), 447.0f);
        const float wr   = src - r0f;
        const int   r0   = (int)r0f;
        const int   r1   = min(r0 + 1, IN_SZ - 1);
        const float mr0  = sig10(r0f - w_off) - sig10(r0f - w_end);
        const float mr1  = sig10((float)r1 - w_off) - sig10((float)r1 - w_end);
        g_b[b * OUT_SZ + j] = make_float2((1.0f - wr) * mr0, wr * mr1);
        g_r[b * OUT_SZ + j] = make_int2(r0, r1);
    }

    // column side (h axis)
    {
        const float step = (h_end - h_off - 1.0f) * (1.0f / 223.0f);
        const float src  = h_off + fj * step;
        const float c0f  = fminf(fmaxf(floorf(src), 0.0f), 447.0f);
        const float wc   = src - c0f;
        const int   c0   = (int)c0f;
        const int   c1   = min(c0 + 1, IN_SZ - 1);
        const float mc0  = sig10(c0f - h_off) - sig10(c0f - h_end);
        const float mc1  = sig10((float)c1 - h_off) - sig10((float)c1 - h_end);
        g_a[b * OUT_SZ + j] = make_float2((1.0f - wc) * mc0, wc * mc1);
        g_c[b * OUT_SZ + j] = make_int2(c0, c1);
    }
}

// ---------------------------------------------------------------------------
// Main gather: barrier-free. Thread = 1 col x 2 rows x 3 channels = 6 pixels,
// 24 independent LDGs front-batched. Block (224,2) covers 4 output rows, all
// channels. grid (56, 64).
// ---------------------------------------------------------------------------
__global__ __launch_bounds__(448, 2) void racnn_gather_kernel(
    const float* __restrict__ img, float* __restrict__ out)
{
    const int b  = blockIdx.y;
    const int jc = threadIdx.x;                            // 0..223
    const int jr = blockIdx.x * 4 + threadIdx.y * 2;       // first of 2 rows

    const float2 a = __ldg(&g_a[b * OUT_SZ + jc]);
    const int2   c = __ldg(&g_c[b * OUT_SZ + jc]);

    const int2   r0 = __ldg(&g_r[b * OUT_SZ + jr]);        // warp-uniform
    const int2   r1 = __ldg(&g_r[b * OUT_SZ + jr + 1]);
    const float2 b0 = __ldg(&g_b[b * OUT_SZ + jr]);
    const float2 b1 = __ldg(&g_b[b * OUT_SZ + jr + 1]);

    const float* base = img + (size_t)b * 3 * PLANE;

    // 8 source addresses (row-pair x col-pair), reused across 3 channels via
    // constant byte offsets folded into the LDG immediate.
    const float* p00 = base + r0.x * IN_SZ + c.x;
    const float* p01 = base + r0.x * IN_SZ + c.y;
    const float* p10 = base + r0.y * IN_SZ + c.x;
    const float* p11 = base + r0.y * IN_SZ + c.y;
    const float* q00 = base + r1.x * IN_SZ + c.x;
    const float* q01 = base + r1.x * IN_SZ + c.y;
    const float* q10 = base + r1.y * IN_SZ + c.x;
    const float* q11 = base + r1.y * IN_SZ + c.y;

    float v[3][8];
    #pragma unroll
    for (int ch = 0; ch < 3; ch++) {
        const int o = ch * PLANE;
        v[ch][0] = __ldg(p00 + o);
        v[ch][1] = __ldg(p01 + o);
        v[ch][2] = __ldg(p10 + o);
        v[ch][3] = __ldg(p11 + o);
        v[ch][4] = __ldg(q00 + o);
        v[ch][5] = __ldg(q01 + o);
        v[ch][6] = __ldg(q10 + o);
        v[ch][7] = __ldg(q11 + o);
    }

    float* obase = out + (size_t)b * 3 * OUT_SZ * OUT_SZ + jr * OUT_SZ + jc;

    #pragma unroll
    for (int ch = 0; ch < 3; ch++) {
        const float t0 = fmaf(a.y, v[ch][1], a.x * v[ch][0]);
        const float u0 = fmaf(a.y, v[ch][3], a.x * v[ch][2]);
        const float t1 = fmaf(a.y, v[ch][5], a.x * v[ch][4]);
        const float u1 = fmaf(a.y, v[ch][7], a.x * v[ch][6]);
        float* op = obase + (size_t)ch * OUT_SZ * OUT_SZ;
        op[0]      = fmaf(b0.y, u0, b0.x * t0);
        op[OUT_SZ] = fmaf(b1.y, u1, b1.x * t1);
    }
}

// ---------------------------------------------------------------------------
extern "C" void kernel_launch(void* const* d_in, const int* in_sizes, int n_in,
                              void* d_out, int out_size)
{
    const float* images = (const float*)d_in[0];
    const float* locs   = (const float*)d_in[1];
    if (n_in >= 2 && in_sizes[0] == BATCH * 3) {
        locs   = (const float*)d_in[0];
        images = (const float*)d_in[1];
    }
    float* out = (float*)d_out;

    racnn_coef_kernel<<<BATCH, OUT_SZ>>>(locs);

    dim3 block(OUT_SZ, 2, 1);        // 448 threads
    dim3 grid(OUT_SZ / 4, BATCH);    // (56, 64)
    racnn_gather_kernel<<<grid, block>>>(images, out);
}

// round 7
// speedup vs baseline: 1.4934x; 1.0022x over previous
#include <cuda_runtime.h>

#define IN_SZ   448
#define OUT_SZ  224
#define BATCH   64
#define RPB     8                 // output rows per block
#define PLANE   (IN_SZ * IN_SZ)

__device__ __forceinline__ float sig10(float z) {
    return 1.0f / (1.0f + __expf(-10.0f * z));
}

// Single fused kernel. Block = (image b, 8 output rows, all 3 channels),
// 448 threads. Phase 0: 232 threads compute separable coefficients -> smem.
// Phase 1: barrier-free gather, 48 independent LDGs per thread
// (1 col x 4 rows x 3 ch), then 36 FMAs + 12 coalesced stores.
__global__ __launch_bounds__(448) void racnn_fused_kernel(
    const float* __restrict__ img, const float* __restrict__ locs,
    float* __restrict__ out)
{
    __shared__ float2 sA[OUT_SZ];    // col (a0, a1), mask folded
    __shared__ int2   sC[OUT_SZ];    // col (c0, c1)
    __shared__ float2 sB[RPB];       // row (b0, b1), mask folded
    __shared__ int2   sR[RPB];       // row (r0, r1)

    const int b       = blockIdx.y;
    const int jr_base = blockIdx.x * RPB;
    const int tid     = threadIdx.y * OUT_SZ + threadIdx.x;

    // ---------------- Phase 0: coefficients (232 threads) ----------------
    if (tid < OUT_SZ + RPB) {
        float tx = __ldg(&locs[b * 3 + 0]);
        float ty = __ldg(&locs[b * 3 + 1]);
        float tl = __ldg(&locs[b * 3 + 2]);

        tl = fmaxf(tl, 448.0f / 3.0f);
        tx = fminf(fmaxf(tx, tl), 448.0f - tl);
        ty = fminf(fmaxf(ty, tl), 448.0f - tl);

        const float w_off = fmaxf(floorf(tx - tl), 0.0f);
        const float h_off = fmaxf(floorf(ty - tl), 0.0f);
        const float w_end = fminf(floorf(tx + tl), 448.0f);
        const float h_end = fminf(floorf(ty + tl), 448.0f);

        if (tid < OUT_SZ) {
            // column side (h axis)
            const float fj   = (float)tid;
            const float step = (h_end - h_off - 1.0f) * (1.0f / 223.0f);
            const float src  = h_off + fj * step;
            const float c0f  = fminf(fmaxf(floorf(src), 0.0f), 447.0f);
            const float wc   = src - c0f;
            const int   c0   = (int)c0f;
            const int   c1   = min(c0 + 1, IN_SZ - 1);
            const float mc0  = sig10(c0f - h_off) - sig10(c0f - h_end);
            const float mc1  = sig10((float)c1 - h_off) - sig10((float)c1 - h_end);
            sA[tid] = make_float2((1.0f - wc) * mc0, wc * mc1);
            sC[tid] = make_int2(c0, c1);
        } else {
            // row side (w axis), 8 rows of this block
            const int   k    = tid - OUT_SZ;
            const float fj   = (float)(jr_base + k);
            const float step = (w_end - w_off - 1.0f) * (1.0f / 223.0f);
            const float src  = w_off + fj * step;
            const float r0f  = fminf(fmaxf(floorf(src), 0.0f), 447.0f);
            const float wr   = src - r0f;
            const int   r0   = (int)r0f;
            const int   r1   = min(r0 + 1, IN_SZ - 1);
            const float mr0  = sig10(r0f - w_off) - sig10(r0f - w_end);
            const float mr1  = sig10((float)r1 - w_off) - sig10((float)r1 - w_end);
            sB[k] = make_float2((1.0f - wr) * mr0, wr * mr1);
            sR[k] = make_int2(r0, r1);
        }
    }
    __syncthreads();

    // ---------------- Phase 1: gather, 4 rows x 3 channels ----------------
    const int jc   = threadIdx.x;            // 0..223
    const int koff = threadIdx.y * 4;        // rows koff..koff+3 (of 8)

    const float2 a = sA[jc];
    const int2   c = sC[jc];
    const int    dc = c.y - c.x;             // 0 or 1

    float2 bb[4];
    int2   rr[4];
    #pragma unroll
    for (int k = 0; k < 4; k++) {
        rr[k] = sR[koff + k];
        bb[k] = sB[koff + k];
    }

    const float* base = img + (size_t)b * 3 * PLANE + c.x;

    // 48 independent loads: 4 rows x (row0,row1) x (c0,c1) x 3 channels.
    float v0[3][8];   // [ch][k*2 + {row0,row1}] at c0
    float v1[3][8];   //                         at c1
    #pragma unroll
    for (int k = 0; k < 4; k++) {
        const float* p0 = base + rr[k].x * IN_SZ;
        const float* p1 = base + rr[k].y * IN_SZ;
        #pragma unroll
        for (int ch = 0; ch < 3; ch++) {
            const int o = ch * PLANE;
            v0[ch][k * 2 + 0] = __ldg(p0 + o);
            v1[ch][k * 2 + 0] = __ldg(p0 + o + dc);
            v0[ch][k * 2 + 1] = __ldg(p1 + o);
            v1[ch][k * 2 + 1] = __ldg(p1 + o + dc);
        }
    }

    float* obase = out + (size_t)b * 3 * OUT_SZ * OUT_SZ
                       + (size_t)(jr_base + koff) * OUT_SZ + jc;

    #pragma unroll
    for (int ch = 0; ch < 3; ch++) {
        float* op = obase + (size_t)ch * OUT_SZ * OUT_SZ;
        #pragma unroll
        for (int k = 0; k < 4; k++) {
            const float top = fmaf(a.y, v1[ch][k * 2 + 0], a.x * v0[ch][k * 2 + 0]);
            const float bot = fmaf(a.y, v1[ch][k * 2 + 1], a.x * v0[ch][k * 2 + 1]);
            op[k * OUT_SZ] = fmaf(bb[k].y, bot, bb[k].x * top);
        }
    }
}

// ---------------------------------------------------------------------------
extern "C" void kernel_launch(void* const* d_in, const int* in_sizes, int n_in,
                              void* d_out, int out_size)
{
    const float* images = (const float*)d_in[0];
    const float* locs   = (const float*)d_in[1];
    if (n_in >= 2 && in_sizes[0] == BATCH * 3) {
        locs   = (const float*)d_in[0];
        images = (const float*)d_in[1];
    }
    float* out = (float*)d_out;

    dim3 block(OUT_SZ, 2, 1);              // 448 threads
    dim3 grid(OUT_SZ / RPB, BATCH, 1);     // (28, 64)
    racnn_fused_kernel<<<grid, block>>>(images, locs, out);
}